// round 9
// baseline (speedup 1.0000x reference)
#include <cuda_runtime.h>
#include <math.h>

#define NBRN  12
#define M_ROWS 18432
#define BA_ROWS 1536
#define F1    128
#define H1    512
#define H2    128
#define FN    64

// weights: base digits (s8) + noise int15 digits (s8), plane-major
__device__ signed char g_B2a[H1*F1], g_B1a[H1*F1], g_B0a[H1*F1];
__device__ signed char g_B2b[H2*H1], g_B1b[H2*H1], g_B0b[H2*H1];
__device__ signed char g_UhA[H1*8*F1], g_UlA[H1*8*F1];
__device__ signed char g_UhB[H2*8*H1], g_UlB[H2*8*H1];
__device__ float g_qW1[H1], g_qU1[H1], g_S1[H1];
__device__ float g_qW2[H2], g_qU2[H2], g_S2[H2];
__device__ float g_h[(size_t)M_ROWS*H1];
__device__ float g_c2[M_ROWS*H2];
__device__ float g_ns[BA_ROWS*FN];
__device__ float g_mean[FN], g_var[FN];
__device__ int g_mn1, g_mx1, g_mn2, g_mx2;

__device__ __forceinline__ void atomicMinF(int* a, float v) {
    if (v >= 0.f) atomicMin(a, __float_as_int(v));
    else atomicMax((unsigned*)a, (unsigned)__float_as_int(v));
}
__device__ __forceinline__ void atomicMaxF(int* a, float v) {
    if (v >= 0.f) atomicMax(a, __float_as_int(v));
    else atomicMin((unsigned*)a, (unsigned)__float_as_int(v));
}
__device__ __forceinline__ void cp_async16(void* s, const void* g) {
    unsigned sa = (unsigned)__cvta_generic_to_shared(s);
    asm volatile("cp.async.cg.shared.global [%0], [%1], 16;\n" :: "r"(sa), "l"(g));
}
__device__ __forceinline__ void ldmx4(unsigned& r0, unsigned& r1, unsigned& r2, unsigned& r3,
                                      const void* p) {
    unsigned a = (unsigned)__cvta_generic_to_shared(p);
    asm volatile("ldmatrix.sync.aligned.m8n8.x4.shared.b16 {%0,%1,%2,%3},[%4];"
                 : "=r"(r0), "=r"(r1), "=r"(r2), "=r"(r3) : "r"(a));
}
__device__ __forceinline__ unsigned qz(float x, float mn, float sc) {
    float t = (x - mn) * sc;
    int q = (int)t; q = q < 0 ? 0 : (q > 255 ? 255 : q);
    return (unsigned)q;
}
__device__ __forceinline__ unsigned bits8(unsigned long long x, int b) {
    return (unsigned)((((x >> b) & 0x0101010101010101ULL) * 0x0102040810204080ULL) >> 56);
}

__global__ void k_init() {
    g_mn1 = 0x7f800000; g_mx1 = (int)0xff800000;
    g_mn2 = 0x7f800000; g_mx2 = (int)0xff800000;
}

#define NODE_N (BA_ROWS*FN)
#define EDGE_N (M_ROWS*64)
__global__ void k_minmax(const float* __restrict__ node, const float* __restrict__ edge) {
    int idx = blockIdx.x * 256 + threadIdx.x;
    float v = (idx < NODE_N) ? node[idx] : edge[idx - NODE_N];
    float mn = v, mx = v;
    #pragma unroll
    for (int o = 16; o; o >>= 1) {
        mn = fminf(mn, __shfl_xor_sync(~0u, mn, o));
        mx = fmaxf(mx, __shfl_xor_sync(~0u, mx, o));
    }
    __shared__ float smn[8], smx[8];
    int lane = threadIdx.x & 31, w = threadIdx.x >> 5;
    if (lane == 0) { smn[w] = mn; smx[w] = mx; }
    __syncthreads();
    if (threadIdx.x == 0) {
        float bmn = smn[0], bmx = smx[0];
        #pragma unroll
        for (int i = 1; i < 8; i++) { bmn = fminf(bmn, smn[i]); bmx = fmaxf(bmx, smx[i]); }
        atomicMinF(&g_mn1, bmn); atomicMaxF(&g_mx1, bmx);
    }
}

// digit decomposition helpers
__device__ __forceinline__ void dig3(float w, float invW, signed char& d2, signed char& d1, signed char& d0) {
    int T = __float2int_rn(w * invW);
    int D2 = (T + 8192) >> 14; int r = T - (D2 << 14);
    int D1 = (r + 64) >> 7;    int D0 = r - (D1 << 7);
    d2 = (signed char)D2; d1 = (signed char)D1; d0 = (signed char)D0;
}
__device__ __forceinline__ void dig2(float u, float invU, signed char& h, signed char& l) {
    int T = __float2int_rn(u * invU);
    int H = (T + 64) >> 7; int L = T - (H << 7);
    h = (signed char)H; l = (signed char)L;
}

__global__ void k_prep1(const float* __restrict__ cond1, const float* __restrict__ eps1) {
    int o = blockIdx.x, i = threadIdx.x;    // 512 x 128
    float w = cond1[o*F1 + i];
    float aw = fabsf(w) * 0.1f;
    float u[8], um = 0.f;
    #pragma unroll
    for (int b = 0; b < 8; b++) {
        u[b] = eps1[b*(H1*F1) + o*F1 + i] * aw;
        um = fmaxf(um, fabsf(u[b]));
    }
    __shared__ float red[128];
    red[i] = fabsf(w); __syncthreads();
    #pragma unroll
    for (int s = 64; s; s >>= 1) { if (i < s) red[i] = fmaxf(red[i], red[i+s]); __syncthreads(); }
    float wmax = fmaxf(red[0], 1e-30f); __syncthreads();
    red[i] = um; __syncthreads();
    #pragma unroll
    for (int s = 64; s; s >>= 1) { if (i < s) red[i] = fmaxf(red[i], red[i+s]); __syncthreads(); }
    float umax = fmaxf(red[0], 1e-30f); __syncthreads();
    red[i] = w + u[7]; __syncthreads();
    #pragma unroll
    for (int s = 64; s; s >>= 1) { if (i < s) red[i] += red[i+s]; __syncthreads(); }
    if (i == 0) { g_S1[o] = red[0]; g_qW1[o] = wmax/2080768.f; g_qU1[o] = umax/16255.f; }
    dig3(w, 2080768.f/wmax, g_B2a[o*F1+i], g_B1a[o*F1+i], g_B0a[o*F1+i]);
    float invU = 16255.f/umax;
    #pragma unroll
    for (int b = 0; b < 8; b++)
        dig2(u[b], invU, g_UhA[o*(8*F1) + b*F1 + i], g_UlA[o*(8*F1) + b*F1 + i]);
}

__global__ void k_prep2(const float* __restrict__ cond2, const float* __restrict__ eps2) {
    int o = blockIdx.x, t = threadIdx.x;    // 128 x 256
    float wv[2], u[2][8], um = 0.f, wm = 0.f, sr = 0.f;
    #pragma unroll
    for (int c = 0; c < 2; c++) {
        int i = t + c*256;
        float w = cond2[o*H1 + i]; wv[c] = w;
        float aw = fabsf(w) * 0.1f;
        sr += cond2[H2*H1 + o*H1 + i] + 0.1f*fabsf(w)*eps2[7*(H2*H1) + o*H1 + i] - 0.1f*fabsf(w)*eps2[7*(H2*H1) + o*H1 + i];
        sr -= 0.f;
        wm = fmaxf(wm, fabsf(w));
        #pragma unroll
        for (int b = 0; b < 8; b++) {
            u[c][b] = eps2[b*(H2*H1) + o*H1 + i] * aw;
            um = fmaxf(um, fabsf(u[c][b]));
        }
    }
    __shared__ float red[256];
    red[t] = wm; __syncthreads();
    #pragma unroll
    for (int s = 128; s; s >>= 1) { if (t < s) red[t] = fmaxf(red[t], red[t+s]); __syncthreads(); }
    float wmax = fmaxf(red[0], 1e-30f); __syncthreads();
    red[t] = um; __syncthreads();
    #pragma unroll
    for (int s = 128; s; s >>= 1) { if (t < s) red[t] = fmaxf(red[t], red[t+s]); __syncthreads(); }
    float umax = fmaxf(red[0], 1e-30f); __syncthreads();
    red[t] = sr; __syncthreads();
    #pragma unroll
    for (int s = 128; s; s >>= 1) { if (t < s) red[t] += red[t+s]; __syncthreads(); }
    if (t == 0) { g_S2[o] = red[0]; g_qW2[o] = wmax/2080768.f; g_qU2[o] = umax/16255.f; }
    float invW = 2080768.f/wmax, invU = 16255.f/umax;
    #pragma unroll
    for (int c = 0; c < 2; c++) {
        int i = t + c*256;
        dig3(wv[c], invW, g_B2b[o*H1+i], g_B1b[o*H1+i], g_B0b[o*H1+i]);
        #pragma unroll
        for (int b = 0; b < 8; b++)
            dig2(u[c][b], invU, g_UhB[o*(8*H1) + b*H1 + i], g_UlB[o*(8*H1) + b*H1 + i]);
    }
}

// ---- int8 GEMM: base (3 digit passes, K=SC) + noise (bit-plane, 2 passes) ----
template<int EPI>
__global__ void __launch_bounds__(256) k_tc(const float* __restrict__ node,
                                            const float* __restrict__ edge) {
    constexpr int SC   = (EPI == 1) ? F1 : H1;
    constexpr int N    = (EPI == 1) ? H1 : H2;
    constexpr int PPS  = SC / 128;        // 128-byte chunks per plane/base
    constexpr int NB   = 3 * PPS;         // base digit stages
    constexpr int NSH  = 8 * PPS;         // noise hi stages
    constexpr int NST  = NB + 2 * NSH;
    constexpr int BPR  = SC/8 + 8;        // bitmap row stride
    constexpr int QROWB = SC + 16;        // q slab row stride
    constexpr int SROWB = 144;
    constexpr int TILE = 128 * SROWB;
    const signed char* B2 = (EPI == 1) ? g_B2a : g_B2b;
    const signed char* B1 = (EPI == 1) ? g_B1a : g_B1b;
    const signed char* B0 = (EPI == 1) ? g_B0a : g_B0b;
    const signed char* Uh = (EPI == 1) ? g_UhA : g_UhB;
    const signed char* Ul = (EPI == 1) ? g_UlA : g_UlB;
    const float* QW = (EPI == 1) ? g_qW1 : g_qW2;
    const float* QU = (EPI == 1) ? g_qU1 : g_qU2;
    const float* S  = (EPI == 1) ? g_S1 : g_S2;
    float* out = (EPI == 1) ? g_h : g_c2;

    extern __shared__ char smraw[];
    char* bsm = smraw;                                       // 3 B tiles
    unsigned char* bp = (unsigned char*)(smraw + 3*TILE);    // bitmaps
    unsigned char* qs = bp + 8*128*BPR;                      // q bytes

    const int tid = threadIdx.x, wid = tid >> 5, lane = tid & 31;
    const int wm = wid >> 1, wn = wid & 1;
    const int g = lane >> 2, ti4 = (lane & 3)*4, ti2 = (lane & 3)*2;
    const int m0 = blockIdx.y * 128, n0 = blockIdx.x * 128;

    float mn, mx;
    if (EPI == 1) { mn = __int_as_float(g_mn1); mx = __int_as_float(g_mx1); }
    else          { mn = __int_as_float(g_mn2); mx = __int_as_float(g_mx2); }
    float qsc = 255.0f / (mx - mn);

    // phase 1: quantize -> q bytes + bitmaps
    constexpr int SEGS = SC / 16;
    #pragma unroll 1
    for (int u = tid; u < 128*SEGS; u += 256) {
        int r = u / SEGS, seg = u % SEGS;
        const float4* p;
        if (EPI == 1) {
            int m = m0 + r;
            if (seg < 4) p = (const float4*)(node + (m/NBRN)*FN + seg*16);
            else         p = (const float4*)(edge + (size_t)m*64 + (seg-4)*16);
        } else {
            p = (const float4*)(g_h + (size_t)(m0 + r)*H1 + seg*16);
        }
        unsigned qw[4];
        #pragma unroll
        for (int j = 0; j < 4; j++) {
            float4 v = p[j];
            qw[j] = qz(v.x,mn,qsc) | (qz(v.y,mn,qsc)<<8) | (qz(v.z,mn,qsc)<<16) | (qz(v.w,mn,qsc)<<24);
        }
        *(uint4*)(qs + r*QROWB + seg*16) = make_uint4(qw[0],qw[1],qw[2],qw[3]);
        unsigned long long x0 = (unsigned long long)qw[0] | ((unsigned long long)qw[1] << 32);
        unsigned long long x1 = (unsigned long long)qw[2] | ((unsigned long long)qw[3] << 32);
        #pragma unroll
        for (int b = 0; b < 8; b++) {
            unsigned short w16 = (unsigned short)(bits8(x0,b) | (bits8(x1,b) << 8));
            *(unsigned short*)(bp + (b*128 + r)*BPR + seg*2) = w16;
        }
    }

    int acc[2][8][4];
    float facc[2][8][4];
    #pragma unroll
    for (int a = 0; a < 2; a++)
        #pragma unroll
        for (int b = 0; b < 8; b++)
            #pragma unroll
            for (int c = 0; c < 4; c++) { acc[a][b][c] = 0; facc[a][b][c] = 0.f; }

    auto loadB = [&](int s) {
        const signed char* W; int rs, koff;
        if (s < NB) {
            int d = s / PPS;
            W = (d == 0) ? B2 : (d == 1) ? B1 : B0;
            rs = SC; koff = (s % PPS) * 128;
        } else {
            int t2 = s - NB;
            if (t2 < NSH) { W = Uh; koff = t2 * 128; }
            else          { W = Ul; koff = (t2 - NSH) * 128; }
            rs = 8 * SC;
        }
        char* bs = bsm + (s % 3) * TILE;
        #pragma unroll
        for (int it = 0; it < 4; it++) {
            int cid = tid + it*256;
            int r = cid >> 3, c = (cid & 7)*16;
            cp_async16(bs + r*SROWB + c, W + (size_t)(n0 + r)*rs + koff + c);
        }
        asm volatile("cp.async.commit_group;\n");
    };

    const int lm = lane >> 3, lr = lane & 7;
    const int lmbase = (wn*64 + (lm>>1)*8 + lr)*SROWB + (lm & 1)*16;
    const int r0a = wm*32 + g;

    loadB(0);
    loadB(1);
    __syncthreads();
    #pragma unroll 1
    for (int s = 0; s < NST; s++) {
        if (s + 1 < NST) asm volatile("cp.async.wait_group 1;\n");
        else             asm volatile("cp.async.wait_group 0;\n");
        __syncthreads();
        if (s + 2 < NST) loadB(s + 2);
        const char* bs = bsm + (s % 3) * TILE;

        if (s < NB) {
            // base stage: A = q bytes
            int i0 = (s % PPS) * 128;
            #pragma unroll
            for (int kk = 0; kk < 4; kk++) {
                unsigned af[2][4], bq[8][2];
                #pragma unroll
                for (int mt = 0; mt < 2; mt++) {
                    int r = r0a + mt*16;
                    const unsigned char* q0 = qs + r*QROWB + i0 + kk*32;
                    const unsigned char* q1 = qs + (r+8)*QROWB + i0 + kk*32;
                    af[mt][0] = *(const unsigned*)(q0 + ti4);
                    af[mt][1] = *(const unsigned*)(q1 + ti4);
                    af[mt][2] = *(const unsigned*)(q0 + 16 + ti4);
                    af[mt][3] = *(const unsigned*)(q1 + 16 + ti4);
                }
                #pragma unroll
                for (int p = 0; p < 4; p++)
                    ldmx4(bq[2*p][0], bq[2*p][1], bq[2*p+1][0], bq[2*p+1][1],
                          bs + lmbase + p*(16*SROWB) + kk*32);
                #pragma unroll
                for (int mt = 0; mt < 2; mt++)
                    #pragma unroll
                    for (int nt = 0; nt < 8; nt++)
                        asm volatile(
                            "mma.sync.aligned.m16n8k32.row.col.s32.u8.s8.s32 "
                            "{%0,%1,%2,%3},{%4,%5,%6,%7},{%8,%9},{%0,%1,%2,%3};"
                            : "+r"(acc[mt][nt][0]), "+r"(acc[mt][nt][1]),
                              "+r"(acc[mt][nt][2]), "+r"(acc[mt][nt][3])
                            : "r"(af[mt][0]), "r"(af[mt][1]), "r"(af[mt][2]), "r"(af[mt][3]),
                              "r"(bq[nt][0]), "r"(bq[nt][1]));
            }
            if ((s % PPS) == PPS - 1) {    // end of digit: fold
                float wdig = (s/PPS == 0) ? 16384.f : (s/PPS == 1) ? 128.f : 1.f;
                #pragma unroll
                for (int a = 0; a < 2; a++)
                    #pragma unroll
                    for (int b = 0; b < 8; b++)
                        #pragma unroll
                        for (int c = 0; c < 4; c++) {
                            facc[a][b][c] += wdig * (float)acc[a][b][c];
                            acc[a][b][c] = 0;
                        }
            }
        } else {
            // noise stage: A = bit * 2^b from bitmaps
            int t2 = s - NB;
            int ks = (t2 < NSH) ? t2 : t2 - NSH;
            int b = ks / PPS, i0 = (ks % PPS) * 16;
            unsigned mult = 0x00204081u << b, mask = 0x01010101u << b;
            unsigned hw[2][2][4];
            #pragma unroll
            for (int mt = 0; mt < 2; mt++)
                #pragma unroll
                for (int hh = 0; hh < 2; hh++) {
                    const unsigned char* q = bp + (b*128 + r0a + mt*16 + hh*8)*BPR + i0;
                    unsigned long long w0 = *(const unsigned long long*)q;
                    unsigned long long w1 = *(const unsigned long long*)(q + 8);
                    hw[mt][hh][0] = (unsigned)w0; hw[mt][hh][1] = (unsigned)(w0 >> 32);
                    hw[mt][hh][2] = (unsigned)w1; hw[mt][hh][3] = (unsigned)(w1 >> 32);
                }
            #pragma unroll
            for (int kk = 0; kk < 4; kk++) {
                unsigned af[2][4], bq[8][2];
                #pragma unroll
                for (int mt = 0; mt < 2; mt++) {
                    af[mt][0] = (((hw[mt][0][kk] >> ti4) & 0xFu) * mult) & mask;
                    af[mt][1] = (((hw[mt][1][kk] >> ti4) & 0xFu) * mult) & mask;
                    af[mt][2] = (((hw[mt][0][kk] >> (16+ti4)) & 0xFu) * mult) & mask;
                    af[mt][3] = (((hw[mt][1][kk] >> (16+ti4)) & 0xFu) * mult) & mask;
                }
                #pragma unroll
                for (int p = 0; p < 4; p++)
                    ldmx4(bq[2*p][0], bq[2*p][1], bq[2*p+1][0], bq[2*p+1][1],
                          bs + lmbase + p*(16*SROWB) + kk*32);
                #pragma unroll
                for (int mt = 0; mt < 2; mt++)
                    #pragma unroll
                    for (int nt = 0; nt < 8; nt++)
                        asm volatile(
                            "mma.sync.aligned.m16n8k32.row.col.s32.u8.s8.s32 "
                            "{%0,%1,%2,%3},{%4,%5,%6,%7},{%8,%9},{%0,%1,%2,%3};"
                            : "+r"(acc[mt][nt][0]), "+r"(acc[mt][nt][1]),
                              "+r"(acc[mt][nt][2]), "+r"(acc[mt][nt][3])
                            : "r"(af[mt][0]), "r"(af[mt][1]), "r"(af[mt][2]), "r"(af[mt][3]),
                              "r"(bq[nt][0]), "r"(bq[nt][1]));
            }
            if (s == NB + NSH - 1) {    // end of noise-hi: acc *= 128
                #pragma unroll
                for (int a = 0; a < 2; a++)
                    #pragma unroll
                    for (int b2 = 0; b2 < 8; b2++)
                        #pragma unroll
                        for (int c = 0; c < 4; c++) acc[a][b2][c] <<= 7;
            }
        }
    }

    // epilogue: z = qW*base + qU*noise, then rescale + bias (+relu/minmax)
    float sc = (mx - mn) * (1.0f / 255.0f);
    float lmn = __int_as_float(0x7f800000), lmx = -lmn;
    #pragma unroll
    for (int mt = 0; mt < 2; mt++)
        #pragma unroll
        for (int nt = 0; nt < 8; nt++)
            #pragma unroll
            for (int c = 0; c < 4; c++) {
                int row = m0 + wm*32 + mt*16 + g + ((c & 2) << 2);
                int col = n0 + wn*64 + nt*8 + ti2 + (c & 1);
                float z = QW[col]*facc[mt][nt][c] + QU[col]*(float)acc[mt][nt][c];
                float hv = z * sc + mn * S[col];
                if (EPI == 1) {
                    hv = fmaxf(hv, 0.f);
                    lmn = fminf(lmn, hv); lmx = fmaxf(lmx, hv);
                }
                out[(size_t)row * N + col] = hv;
            }
    if (EPI == 1) {
        #pragma unroll
        for (int o = 16; o; o >>= 1) {
            lmn = fminf(lmn, __shfl_xor_sync(~0u, lmn, o));
            lmx = fmaxf(lmx, __shfl_xor_sync(~0u, lmx, o));
        }
        if (lane == 0) { atomicMinF(&g_mn2, lmn); atomicMaxF(&g_mx2, lmx); }
    }
}

__global__ void k_gate(const float* __restrict__ mask) {
    int idx = blockIdx.x * 256 + threadIdx.x;
    int ba = idx >> 6, j = idx & 63;
    float acc = 0.f;
    #pragma unroll
    for (int nb = 0; nb < NBRN; nb++) {
        int m = ba*NBRN + nb;
        float gv = g_c2[m*H2 + j], ev = g_c2[m*H2 + 64 + j];
        acc += (1.f/(1.f + expf(-gv))) * tanhf(ev) * mask[m];
    }
    g_ns[idx] = acc;
}

__global__ void k_stats() {
    int j = blockIdx.x, t = threadIdx.x;
    __shared__ float red[256];
    __shared__ float mean_s;
    float s = 0.f;
    for (int r = t; r < BA_ROWS; r += 256) s += g_ns[r*FN + j];
    red[t] = s; __syncthreads();
    #pragma unroll
    for (int k = 128; k; k >>= 1) { if (t < k) red[t] += red[t+k]; __syncthreads(); }
    if (t == 0) mean_s = red[0] / (float)BA_ROWS;
    __syncthreads();
    float mean = mean_s, s2 = 0.f;
    for (int r = t; r < BA_ROWS; r += 256) { float d = g_ns[r*FN + j] - mean; s2 += d*d; }
    red[t] = s2; __syncthreads();
    #pragma unroll
    for (int k = 128; k; k >>= 1) { if (t < k) red[t] += red[t+k]; __syncthreads(); }
    if (t == 0) { g_mean[j] = mean; g_var[j] = red[0] / (float)BA_ROWS; }
}

__global__ void k_final(const float* __restrict__ node, const float* __restrict__ gamma,
                        const float* __restrict__ beta, float* __restrict__ out) {
    int idx = blockIdx.x * 256 + threadIdx.x;
    int j = idx & 63;
    float bn = (g_ns[idx] - g_mean[j]) / sqrtf(g_var[j] + 1e-5f) * gamma[j] + beta[j];
    out[idx] = fmaxf(node[idx] + bn, 0.f);
}

extern "C" void kernel_launch(void* const* d_in, const int* in_sizes, int n_in,
                              void* d_out, int out_size) {
    const float* node  = (const float*)d_in[0];
    const float* edge  = (const float*)d_in[1];
    const float* maskp = (const float*)d_in[2];
    const float* cond1 = (const float*)d_in[3];
    const float* cond2 = (const float*)d_in[4];
    const float* eps1  = (const float*)d_in[5];
    const float* eps2  = (const float*)d_in[6];
    const float* gamma = (const float*)d_in[7];
    const float* beta  = (const float*)d_in[8];
    float* out = (float*)d_out;

    const int SMEM1 = 3*128*144 + 8*128*(F1/8+8) + 128*(F1+16);   // 98304
    const int SMEM2 = 3*128*144 + 8*128*(H1/8+8) + 128*(H1+16);   // 196608
    cudaFuncSetAttribute(k_tc<1>, cudaFuncAttributeMaxDynamicSharedMemorySize, SMEM1);
    cudaFuncSetAttribute(k_tc<2>, cudaFuncAttributeMaxDynamicSharedMemorySize, SMEM2);

    k_init<<<1, 1>>>();
    k_minmax<<<(NODE_N + EDGE_N)/256, 256>>>(node, edge);
    k_prep1<<<H1, 128>>>(cond1, eps1);
    k_prep2<<<H2, 256>>>(cond2, eps2);
    k_tc<1><<<dim3(H1/128, M_ROWS/128), 256, SMEM1>>>(node, edge);
    k_tc<2><<<dim3(1, M_ROWS/128), 256, SMEM2>>>(nullptr, nullptr);
    k_gate<<<(BA_ROWS*FN)/256, 256>>>(maskp);
    k_stats<<<FN, 256>>>();
    k_final<<<(BA_ROWS*FN)/256, 256>>>(node, gamma, beta, out);
}

// round 10
// speedup vs baseline: 3.2405x; 3.2405x over previous
#include <cuda_runtime.h>
#include <cuda_fp16.h>
#include <math.h>

#define NBRN  12
#define M_ROWS 18432
#define BA_ROWS 1536
#define F1    128
#define H1    512
#define H2    128
#define FN    64

// ---------------- scratch ----------------
// layer-1 weights split node/edge, plane-major k = b*64 + i (fp16 hi; lo planes 4..7)
__device__ __half g_W1Nh[H1 * 512], g_W1Nl[H1 * 256];
__device__ __half g_W1Eh[H1 * 512], g_W1El[H1 * 256];
__device__ __half g_W2h[H2 * 4096], g_W2l[H2 * 2048];
__device__ float  g_S1[H1], g_S2[H2];
__device__ float  g_zn[BA_ROWS * H1];          // node-part raw partial sums
__device__ float  g_h[(size_t)M_ROWS * H1];
__device__ float  g_c2[M_ROWS * H2];
__device__ float  g_ns[BA_ROWS * FN];
__device__ float  g_mean[FN], g_var[FN];
__device__ int    g_mn1, g_mx1, g_mn2, g_mx2;  // float bits

// ---------------- helpers ----------------
__device__ __forceinline__ void atomicMinF(int* a, float v) {
    if (v >= 0.f) atomicMin(a, __float_as_int(v));
    else          atomicMax((unsigned*)a, (unsigned)__float_as_int(v));
}
__device__ __forceinline__ void atomicMaxF(int* a, float v) {
    if (v >= 0.f) atomicMax(a, __float_as_int(v));
    else          atomicMin((unsigned*)a, (unsigned)__float_as_int(v));
}
__device__ __forceinline__ void cp_async16(void* s, const void* g) {
    unsigned sa = (unsigned)__cvta_generic_to_shared(s);
    asm volatile("cp.async.cg.shared.global [%0], [%1], 16;\n" :: "r"(sa), "l"(g));
}
__device__ __forceinline__ void ldmx4(unsigned& r0, unsigned& r1, unsigned& r2, unsigned& r3,
                                      const __half* p) {
    unsigned a = (unsigned)__cvta_generic_to_shared(p);
    asm volatile("ldmatrix.sync.aligned.m8n8.x4.shared.b16 {%0,%1,%2,%3},[%4];"
                 : "=r"(r0), "=r"(r1), "=r"(r2), "=r"(r3) : "r"(a));
}
__device__ __forceinline__ unsigned qz(float x, float mn, float sc) {
    float t = (x - mn) * sc;
    int q = (int)t; q = q < 0 ? 0 : (q > 255 ? 255 : q);
    return (unsigned)q;
}
__device__ __forceinline__ unsigned bits8(unsigned long long x, int b) {
    return (unsigned)((((x >> b) & 0x0101010101010101ULL) * 0x0102040810204080ULL) >> 56);
}

// ---------------- small kernels ----------------
__global__ void k_init() {
    g_mn1 = 0x7f800000; g_mx1 = (int)0xff800000;
    g_mn2 = 0x7f800000; g_mx2 = (int)0xff800000;
}

#define NODE_N (BA_ROWS * FN)
#define EDGE_N (M_ROWS * 64)
__global__ void k_minmax(const float* __restrict__ node, const float* __restrict__ edge) {
    int idx = blockIdx.x * 256 + threadIdx.x;
    float v = (idx < NODE_N) ? node[idx] : edge[idx - NODE_N];
    float mn = v, mx = v;
    #pragma unroll
    for (int o = 16; o; o >>= 1) {
        mn = fminf(mn, __shfl_xor_sync(~0u, mn, o));
        mx = fmaxf(mx, __shfl_xor_sync(~0u, mx, o));
    }
    __shared__ float smn[8], smx[8];
    int lane = threadIdx.x & 31, w = threadIdx.x >> 5;
    if (lane == 0) { smn[w] = mn; smx[w] = mx; }
    __syncthreads();
    if (threadIdx.x == 0) {
        float bmn = smn[0], bmx = smx[0];
        #pragma unroll
        for (int i = 1; i < 8; i++) { bmn = fminf(bmn, smn[i]); bmx = fmaxf(bmx, smx[i]); }
        atomicMinF(&g_mn1, bmn); atomicMaxF(&g_mx1, bmx);
    }
}

// layer-1 weights: fp16(2^b*(w+eps*|w|*0.1)), split node (i<64) / edge (i>=64),
// plane-major k=b*64+i; lo residual planes 4..7 only.
__global__ void k_prep1(const float* __restrict__ cond1, const float* __restrict__ eps1) {
    int o = blockIdx.x, i = threadIdx.x;        // 512 x 128
    float w = cond1[o * F1 + i];
    float aw = fabsf(w) * 0.1f;
    float s7 = 0.f;
    int isn = (i < 64), il = i & 63;
    #pragma unroll
    for (int b = 0; b < 8; b++) {
        float wn = w + eps1[b * (H1 * F1) + o * F1 + i] * aw;
        if (b == 7) s7 = wn;
        float v = wn * (float)(1 << b);
        __half hi = __float2half_rn(v);
        if (isn) g_W1Nh[o * 512 + b * 64 + il] = hi;
        else     g_W1Eh[o * 512 + b * 64 + il] = hi;
        if (b >= 4) {
            __half lo = __float2half_rn(v - __half2float(hi));
            if (isn) g_W1Nl[o * 256 + (b - 4) * 64 + il] = lo;
            else     g_W1El[o * 256 + (b - 4) * 64 + il] = lo;
        }
    }
    __shared__ float red[128];
    red[i] = s7; __syncthreads();
    #pragma unroll
    for (int s = 64; s; s >>= 1) { if (i < s) red[i] += red[i + s]; __syncthreads(); }
    if (i == 0) g_S1[o] = red[0];
}

__global__ void k_prep2(const float* __restrict__ cond2, const float* __restrict__ eps2) {
    int o = blockIdx.x, t = threadIdx.x;        // 128 x 256
    float sr = 0.f;
    for (int i = t; i < H1; i += 256) {
        float w = cond2[o * H1 + i];
        float aw = fabsf(w) * 0.1f;
        sr += cond2[H2 * H1 + o * H1 + i];
        #pragma unroll
        for (int b = 0; b < 8; b++) {
            float wn = w + eps2[b * (H2 * H1) + o * H1 + i] * aw;
            float v = wn * (float)(1 << b);
            __half hi = __float2half_rn(v);
            g_W2h[o * 4096 + b * H1 + i] = hi;
            if (b >= 4)
                g_W2l[o * 2048 + (b - 4) * H1 + i] = __float2half_rn(v - __half2float(hi));
        }
    }
    __shared__ float red[256];
    red[t] = sr; __syncthreads();
    #pragma unroll
    for (int s = 128; s; s >>= 1) { if (t < s) red[t] += red[t + s]; __syncthreads(); }
    if (t == 0) g_S2[o] = red[0];
}

// ---------------- fused bit-plane GEMM (fp16 HMMA, plane-major) ----------------
// EPI=0: node GEMM (M=1536, SC=64) -> raw sums g_zn.
// EPI=1: edge GEMM (M=18432, SC=64) -> g_h = relu((accE+zn)*sc + bias), minmax.
// EPI=2: layer-2 GEMM (SC=512) -> g_c2.
template<int EPI>
__global__ void __launch_bounds__(256) k_tc(const float* __restrict__ node,
                                            const float* __restrict__ edge) {
    constexpr int SC  = (EPI == 2) ? 512 : 64;
    constexpr int N   = (EPI == 2) ? H2 : H1;
    constexpr int SPP = SC / 64;
    constexpr int KTH = 8 * SPP;
    constexpr int KTL = 4 * SPP;
    constexpr int NST = KTH + KTL;
    constexpr int KHI = 8 * SC, KLO = 4 * SC;
    constexpr int QROWB = SC + 16;
    constexpr int BPR   = SC / 8 + 8;
    constexpr int SROW  = 72;
    constexpr int BTILE = 128 * SROW;
    const __half* Whi = (EPI == 0) ? g_W1Nh : (EPI == 1) ? g_W1Eh : g_W2h;
    const __half* Wlo = (EPI == 0) ? g_W1Nl : (EPI == 1) ? g_W1El : g_W2l;
    const float*  S   = (EPI == 2) ? g_S2 : g_S1;
    float* out = (EPI == 0) ? g_zn : (EPI == 1) ? g_h : g_c2;

    extern __shared__ char smraw[];
    __half*        bsm = (__half*)smraw;                          // 3 B tiles
    unsigned char* bp  = (unsigned char*)(smraw + 3 * BTILE * 2); // bitmaps
    unsigned char* qs  = bp + 8 * 128 * BPR;                      // q slab

    const int tid = threadIdx.x, wid = tid >> 5, lane = tid & 31;
    const int wm = wid >> 1, wn = wid & 1;
    const int g = lane >> 2, ti2 = (lane & 3) * 2;
    const int m0 = blockIdx.y * 128, n0 = blockIdx.x * 128;

    float mn, mx;
    if (EPI == 2) { mn = __int_as_float(g_mn2); mx = __int_as_float(g_mx2); }
    else          { mn = __int_as_float(g_mn1); mx = __int_as_float(g_mx1); }
    float qsc = 255.0f / (mx - mn);

    // ---- phase 1: quantize source slab -> q bytes + bitmaps ----
    constexpr int SEGS = SC / 16;
    #pragma unroll 1
    for (int u = tid; u < 128 * SEGS; u += 256) {
        int r = u / SEGS, seg = u % SEGS;
        const float4* p;
        if (EPI == 0)      p = (const float4*)(node + (m0 + r) * FN + seg * 16);
        else if (EPI == 1) p = (const float4*)(edge + (size_t)(m0 + r) * 64 + seg * 16);
        else               p = (const float4*)(g_h + (size_t)(m0 + r) * H1 + seg * 16);
        unsigned qw[4];
        #pragma unroll
        for (int j = 0; j < 4; j++) {
            float4 v = p[j];
            qw[j] = qz(v.x, mn, qsc) | (qz(v.y, mn, qsc) << 8) |
                    (qz(v.z, mn, qsc) << 16) | (qz(v.w, mn, qsc) << 24);
        }
        unsigned long long x0 = (unsigned long long)qw[0] | ((unsigned long long)qw[1] << 32);
        unsigned long long x1 = (unsigned long long)qw[2] | ((unsigned long long)qw[3] << 32);
        #pragma unroll
        for (int b = 0; b < 8; b++) {
            unsigned short w16 = (unsigned short)(bits8(x0, b) | (bits8(x1, b) << 8));
            *(unsigned short*)(bp + (b * 128 + r) * BPR + seg * 2) = w16;
        }
        (void)qs;
    }

    // ---- k-loop ----
    float acc[2][8][4];
    #pragma unroll
    for (int a = 0; a < 2; a++)
        #pragma unroll
        for (int b = 0; b < 8; b++)
            #pragma unroll
            for (int c = 0; c < 4; c++) acc[a][b][c] = 0.f;

    auto loadB = [&](int s) {
        const __half* W; int rs, kofs;
        if (s < KTH) { W = Whi; rs = KHI; kofs = s * 64; }
        else         { W = Wlo; rs = KLO; kofs = (s - KTH) * 64; }
        __half* bs = bsm + (s % 3) * BTILE;
        #pragma unroll
        for (int it2 = 0; it2 < 4; it2++) {
            int cid = tid + it2 * 256;
            int r = cid >> 3, c = (cid & 7) * 8;
            cp_async16(&bs[r * SROW + c], W + (size_t)(n0 + r) * rs + kofs + c);
        }
        asm volatile("cp.async.commit_group;\n");
    };

    const int lm = lane >> 3, lr = lane & 7;
    const int lmbase = (wn * 64 + (lm >> 1) * 8 + lr) * SROW + (lm & 1) * 8;

    loadB(0);
    loadB(1);
    __syncthreads();   // also covers bitmap writes
    #pragma unroll 1
    for (int s = 0; s < NST; s++) {
        if (s + 1 < NST) asm volatile("cp.async.wait_group 1;\n");
        else             asm volatile("cp.async.wait_group 0;\n");
        __syncthreads();
        if (s + 2 < NST) loadB(s + 2);

        int b, i0;
        if (s < KTH) { b = s / SPP; i0 = (s % SPP) * 64; }
        else         { int s2 = s - KTH; b = 4 + s2 / SPP; i0 = (s2 % SPP) * 64; }
        int bofs = b * 128;

        unsigned long long wt0[2], wt8[2];
        #pragma unroll
        for (int mt = 0; mt < 2; mt++) {
            int r0 = wm * 32 + mt * 16 + g;
            wt0[mt] = (*(const unsigned long long*)(bp + (bofs + r0) * BPR + (i0 >> 3))) >> ti2;
            wt8[mt] = (*(const unsigned long long*)(bp + (bofs + r0 + 8) * BPR + (i0 >> 3))) >> ti2;
        }
        const __half* bs = bsm + (s % 3) * BTILE;

        #pragma unroll
        for (int kk = 0; kk < 4; kk++) {
            unsigned af[2][4];
            #pragma unroll
            for (int mt = 0; mt < 2; mt++) {
                unsigned lo0 = (unsigned)(wt0[mt] >> (kk * 16));
                unsigned lo1 = (unsigned)(wt8[mt] >> (kk * 16));
                af[mt][0] = (lo0 & 1u) * 0x3C00u | ((lo0 >> 1) & 1u) * 0x3C000000u;
                af[mt][1] = (lo1 & 1u) * 0x3C00u | ((lo1 >> 1) & 1u) * 0x3C000000u;
                af[mt][2] = ((lo0 >> 8) & 1u) * 0x3C00u | ((lo0 >> 9) & 1u) * 0x3C000000u;
                af[mt][3] = ((lo1 >> 8) & 1u) * 0x3C00u | ((lo1 >> 9) & 1u) * 0x3C000000u;
            }
            unsigned bq[8][2];
            #pragma unroll
            for (int p = 0; p < 4; p++)
                ldmx4(bq[2 * p][0], bq[2 * p][1], bq[2 * p + 1][0], bq[2 * p + 1][1],
                      bs + lmbase + p * (16 * SROW) + kk * 16);
            #pragma unroll
            for (int mt = 0; mt < 2; mt++)
                #pragma unroll
                for (int nt = 0; nt < 8; nt++)
                    asm volatile(
                        "mma.sync.aligned.m16n8k16.row.col.f32.f16.f16.f32 "
                        "{%0,%1,%2,%3},{%4,%5,%6,%7},{%8,%9},{%0,%1,%2,%3};"
                        : "+f"(acc[mt][nt][0]), "+f"(acc[mt][nt][1]),
                          "+f"(acc[mt][nt][2]), "+f"(acc[mt][nt][3])
                        : "r"(af[mt][0]), "r"(af[mt][1]), "r"(af[mt][2]), "r"(af[mt][3]),
                          "r"(bq[nt][0]), "r"(bq[nt][1]));
        }
    }

    // ---- epilogue ----
    if (EPI == 0) {
        // raw partial sums, no scaling
        #pragma unroll
        for (int mt = 0; mt < 2; mt++)
            #pragma unroll
            for (int nt = 0; nt < 8; nt++)
                #pragma unroll
                for (int c = 0; c < 4; c++) {
                    int row = m0 + wm * 32 + mt * 16 + g + ((c & 2) << 2);
                    int col = n0 + wn * 64 + nt * 8 + ti2 + (c & 1);
                    out[row * H1 + col] = acc[mt][nt][c];
                }
    } else if (EPI == 1) {
        float sc = (mx - mn) * (1.0f / 255.0f);
        float lmn = __int_as_float(0x7f800000), lmx = -lmn;
        #pragma unroll
        for (int mt = 0; mt < 2; mt++)
            #pragma unroll
            for (int nt = 0; nt < 8; nt++)
                #pragma unroll
                for (int c = 0; c < 4; c++) {
                    int row = m0 + wm * 32 + mt * 16 + g + ((c & 2) << 2);
                    int col = n0 + wn * 64 + nt * 8 + ti2 + (c & 1);
                    float z = acc[mt][nt][c] + g_zn[(row / NBRN) * H1 + col];
                    float hv = z * sc + mn * S[col];
                    hv = fmaxf(hv, 0.f);
                    out[(size_t)row * N + col] = hv;
                    lmn = fminf(lmn, hv); lmx = fmaxf(lmx, hv);
                }
        #pragma unroll
        for (int o = 16; o; o >>= 1) {
            lmn = fminf(lmn, __shfl_xor_sync(~0u, lmn, o));
            lmx = fmaxf(lmx, __shfl_xor_sync(~0u, lmx, o));
        }
        if (lane == 0) { atomicMinF(&g_mn2, lmn); atomicMaxF(&g_mx2, lmx); }
    } else {
        float sc = (mx - mn) * (1.0f / 255.0f);
        #pragma unroll
        for (int mt = 0; mt < 2; mt++)
            #pragma unroll
            for (int nt = 0; nt < 8; nt++)
                #pragma unroll
                for (int c = 0; c < 4; c++) {
                    int row = m0 + wm * 32 + mt * 16 + g + ((c & 2) << 2);
                    int col = n0 + wn * 64 + nt * 8 + ti2 + (c & 1);
                    out[(size_t)row * N + col] = acc[mt][nt][c] * sc + mn * S[col];
                }
    }
}

// sigmoid(gate)*tanh(extract)*mask, summed over 12 neighbors
__global__ void k_gate(const float* __restrict__ mask) {
    int idx = blockIdx.x * 256 + threadIdx.x;
    int ba = idx >> 6, j = idx & 63;
    float acc = 0.f;
    #pragma unroll
    for (int nb = 0; nb < NBRN; nb++) {
        int m = ba * NBRN + nb;
        float gv = g_c2[m * H2 + j];
        float ev = g_c2[m * H2 + 64 + j];
        acc += (1.f / (1.f + expf(-gv))) * tanhf(ev) * mask[m];
    }
    g_ns[idx] = acc;
}

// deterministic per-feature BN statistics
__global__ void k_stats() {
    int j = blockIdx.x, t = threadIdx.x;
    __shared__ float red[256];
    __shared__ float mean_s;
    float s = 0.f;
    for (int r = t; r < BA_ROWS; r += 256) s += g_ns[r * FN + j];
    red[t] = s; __syncthreads();
    #pragma unroll
    for (int k = 128; k; k >>= 1) { if (t < k) red[t] += red[t + k]; __syncthreads(); }
    if (t == 0) mean_s = red[0] / (float)BA_ROWS;
    __syncthreads();
    float mean = mean_s, s2 = 0.f;
    for (int r = t; r < BA_ROWS; r += 256) { float d = g_ns[r * FN + j] - mean; s2 += d * d; }
    red[t] = s2; __syncthreads();
    #pragma unroll
    for (int k = 128; k; k >>= 1) { if (t < k) red[t] += red[t + k]; __syncthreads(); }
    if (t == 0) { g_mean[j] = mean; g_var[j] = red[0] / (float)BA_ROWS; }
}

__global__ void k_final(const float* __restrict__ node, const float* __restrict__ gamma,
                        const float* __restrict__ beta, float* __restrict__ out) {
    int idx = blockIdx.x * 256 + threadIdx.x;
    int j = idx & 63;
    float bn = (g_ns[idx] - g_mean[j]) / sqrtf(g_var[j] + 1e-5f) * gamma[j] + beta[j];
    out[idx] = fmaxf(node[idx] + bn, 0.f);
}

// ---------------- launcher ----------------
extern "C" void kernel_launch(void* const* d_in, const int* in_sizes, int n_in,
                              void* d_out, int out_size) {
    const float* node  = (const float*)d_in[0];
    const float* edge  = (const float*)d_in[1];
    const float* maskp = (const float*)d_in[2];
    const float* cond1 = (const float*)d_in[3];
    const float* cond2 = (const float*)d_in[4];
    const float* eps1  = (const float*)d_in[5];
    const float* eps2  = (const float*)d_in[6];
    const float* gamma = (const float*)d_in[7];
    const float* beta  = (const float*)d_in[8];
    float* out = (float*)d_out;

    // smem: 3 B tiles + bitmaps + q slab
    const int SMEM01 = 3 * 128 * 72 * 2 + 8 * 128 * (64 / 8 + 8) + 128 * (64 + 16);    // 81920
    const int SMEM2  = 3 * 128 * 72 * 2 + 8 * 128 * (512 / 8 + 8) + 128 * (512 + 16);  // 196608
    cudaFuncSetAttribute(k_tc<0>, cudaFuncAttributeMaxDynamicSharedMemorySize, SMEM01);
    cudaFuncSetAttribute(k_tc<1>, cudaFuncAttributeMaxDynamicSharedMemorySize, SMEM01);
    cudaFuncSetAttribute(k_tc<2>, cudaFuncAttributeMaxDynamicSharedMemorySize, SMEM2);

    k_init<<<1, 1>>>();
    k_minmax<<<(NODE_N + EDGE_N) / 256, 256>>>(node, edge);
    k_prep1<<<H1, 128>>>(cond1, eps1);
    k_prep2<<<H2, 256>>>(cond2, eps2);
    k_tc<0><<<dim3(H1 / 128, BA_ROWS / 128), 256, SMEM01>>>(node, edge);
    k_tc<1><<<dim3(H1 / 128, M_ROWS / 128), 256, SMEM01>>>(node, edge);
    k_tc<2><<<dim3(1, M_ROWS / 128), 256, SMEM2>>>(nullptr, nullptr);
    k_gate<<<(BA_ROWS * FN) / 256, 256>>>(maskp);
    k_stats<<<FN, 256>>>();
    k_final<<<(BA_ROWS * FN) / 256, 256>>>(node, gamma, beta, out);
}

// round 12
// speedup vs baseline: 3.3284x; 1.0271x over previous
#include <cuda_runtime.h>
#include <cuda_fp16.h>
#include <math.h>

#define NBRN  12
#define M_ROWS 18432
#define BA_ROWS 1536
#define F1    128
#define H1    512
#define H2    128
#define FN    64

// ---------------- scratch ----------------
// layer-1 weights split node/edge, plane-major k = b*64 + i (fp16 hi; lo planes 4..7)
__device__ __half g_W1Nh[H1 * 512], g_W1Nl[H1 * 256];
__device__ __half g_W1Eh[H1 * 512], g_W1El[H1 * 256];
__device__ __half g_W2h[H2 * 4096], g_W2l[H2 * 2048];
__device__ float  g_S1[H1], g_S2[H2];
__device__ float  g_zn[BA_ROWS * H1];          // node-part raw partial sums
__device__ float  g_h[(size_t)M_ROWS * H1];
__device__ float  g_c2[M_ROWS * H2];
__device__ float  g_ns[BA_ROWS * FN];
__device__ float  g_mean[FN], g_var[FN];
__device__ int    g_mn1, g_mx1, g_mn2, g_mx2;  // float bits

// ---------------- helpers ----------------
__device__ __forceinline__ void atomicMinF(int* a, float v) {
    if (v >= 0.f) atomicMin(a, __float_as_int(v));
    else          atomicMax((unsigned*)a, (unsigned)__float_as_int(v));
}
__device__ __forceinline__ void atomicMaxF(int* a, float v) {
    if (v >= 0.f) atomicMax(a, __float_as_int(v));
    else          atomicMin((unsigned*)a, (unsigned)__float_as_int(v));
}
__device__ __forceinline__ void cp_async16(void* s, const void* g) {
    unsigned sa = (unsigned)__cvta_generic_to_shared(s);
    asm volatile("cp.async.cg.shared.global [%0], [%1], 16;\n" :: "r"(sa), "l"(g));
}
__device__ __forceinline__ void ldmx4(unsigned& r0, unsigned& r1, unsigned& r2, unsigned& r3,
                                      const __half* p) {
    unsigned a = (unsigned)__cvta_generic_to_shared(p);
    asm volatile("ldmatrix.sync.aligned.m8n8.x4.shared.b16 {%0,%1,%2,%3},[%4];"
                 : "=r"(r0), "=r"(r1), "=r"(r2), "=r"(r3) : "r"(a));
}
__device__ __forceinline__ unsigned qz(float x, float mn, float sc) {
    float t = (x - mn) * sc;
    int q = (int)t; q = q < 0 ? 0 : (q > 255 ? 255 : q);
    return (unsigned)q;
}
__device__ __forceinline__ unsigned bits8(unsigned long long x, int b) {
    return (unsigned)((((x >> b) & 0x0101010101010101ULL) * 0x0102040810204080ULL) >> 56);
}

// ---------------- small kernels ----------------
__global__ void k_init() {
    g_mn1 = 0x7f800000; g_mx1 = (int)0xff800000;
    g_mn2 = 0x7f800000; g_mx2 = (int)0xff800000;
}

#define NODE_N (BA_ROWS * FN)
#define EDGE_N (M_ROWS * 64)
__global__ void k_minmax(const float* __restrict__ node, const float* __restrict__ edge) {
    int idx = blockIdx.x * 256 + threadIdx.x;
    float v = (idx < NODE_N) ? node[idx] : edge[idx - NODE_N];
    float mn = v, mx = v;
    #pragma unroll
    for (int o = 16; o; o >>= 1) {
        mn = fminf(mn, __shfl_xor_sync(~0u, mn, o));
        mx = fmaxf(mx, __shfl_xor_sync(~0u, mx, o));
    }
    __shared__ float smn[8], smx[8];
    int lane = threadIdx.x & 31, w = threadIdx.x >> 5;
    if (lane == 0) { smn[w] = mn; smx[w] = mx; }
    __syncthreads();
    if (threadIdx.x == 0) {
        float bmn = smn[0], bmx = smx[0];
        #pragma unroll
        for (int i = 1; i < 8; i++) { bmn = fminf(bmn, smn[i]); bmx = fmaxf(bmx, smx[i]); }
        atomicMinF(&g_mn1, bmn); atomicMaxF(&g_mx1, bmx);
    }
}

// layer-1 weights: fp16(2^b*(w+eps*|w|*0.1)), split node (i<64) / edge (i>=64),
// plane-major k=b*64+i; lo residual planes 4..7 only.
__global__ void k_prep1(const float* __restrict__ cond1, const float* __restrict__ eps1) {
    int o = blockIdx.x, i = threadIdx.x;        // 512 x 128
    float w = cond1[o * F1 + i];
    float aw = fabsf(w) * 0.1f;
    float s7 = 0.f;
    int isn = (i < 64), il = i & 63;
    #pragma unroll
    for (int b = 0; b < 8; b++) {
        float wn = w + eps1[b * (H1 * F1) + o * F1 + i] * aw;
        if (b == 7) s7 = wn;
        float v = wn * (float)(1 << b);
        __half hi = __float2half_rn(v);
        if (isn) g_W1Nh[o * 512 + b * 64 + il] = hi;
        else     g_W1Eh[o * 512 + b * 64 + il] = hi;
        if (b >= 4) {
            __half lo = __float2half_rn(v - __half2float(hi));
            if (isn) g_W1Nl[o * 256 + (b - 4) * 64 + il] = lo;
            else     g_W1El[o * 256 + (b - 4) * 64 + il] = lo;
        }
    }
    __shared__ float red[128];
    red[i] = s7; __syncthreads();
    #pragma unroll
    for (int s = 64; s; s >>= 1) { if (i < s) red[i] += red[i + s]; __syncthreads(); }
    if (i == 0) g_S1[o] = red[0];
}

__global__ void k_prep2(const float* __restrict__ cond2, const float* __restrict__ eps2) {
    int o = blockIdx.x, t = threadIdx.x;        // 128 x 256
    float sr = 0.f;
    for (int i = t; i < H1; i += 256) {
        float w = cond2[o * H1 + i];
        float aw = fabsf(w) * 0.1f;
        sr += cond2[H2 * H1 + o * H1 + i];
        #pragma unroll
        for (int b = 0; b < 8; b++) {
            float wn = w + eps2[b * (H2 * H1) + o * H1 + i] * aw;
            float v = wn * (float)(1 << b);
            __half hi = __float2half_rn(v);
            g_W2h[o * 4096 + b * H1 + i] = hi;
            if (b >= 4)
                g_W2l[o * 2048 + (b - 4) * H1 + i] = __float2half_rn(v - __half2float(hi));
        }
    }
    __shared__ float red[256];
    red[t] = sr; __syncthreads();
    #pragma unroll
    for (int s = 128; s; s >>= 1) { if (t < s) red[t] += red[t + s]; __syncthreads(); }
    if (t == 0) g_S2[o] = red[0];
}

// ---------------- fused bit-plane GEMM (fp16 HMMA, plane-major) ----------------
// A tile (128x64 binary fp16) expanded CTA-wide from bitmaps into smem each stage
// (double-buffered), consumed via ldmatrix. B via 3-deep cp.async ring.
// EPI=0: node GEMM (M=1536, SC=64) -> raw sums g_zn.
// EPI=1: edge GEMM (M=18432, SC=64) -> g_h = relu((accE+zn)*sc + bias), minmax.
// EPI=2: layer-2 GEMM (SC=512) -> g_c2.
template<int EPI>
__global__ void __launch_bounds__(256) k_tc(const float* __restrict__ node,
                                            const float* __restrict__ edge) {
    constexpr int SC  = (EPI == 2) ? 512 : 64;
    constexpr int N   = (EPI == 2) ? H2 : H1;
    constexpr int SPP = SC / 64;
    constexpr int KTH = 8 * SPP;
    constexpr int KTL = 4 * SPP;
    constexpr int NST = KTH + KTL;
    constexpr int KHI = 8 * SC, KLO = 4 * SC;
    constexpr int BPR   = SC / 8 + 8;
    constexpr int SROW  = 72;
    constexpr int BTILE = 128 * SROW;
    const __half* Whi = (EPI == 0) ? g_W1Nh : (EPI == 1) ? g_W1Eh : g_W2h;
    const __half* Wlo = (EPI == 0) ? g_W1Nl : (EPI == 1) ? g_W1El : g_W2l;
    const float*  S   = (EPI == 2) ? g_S2 : g_S1;
    float* out = (EPI == 0) ? g_zn : (EPI == 1) ? g_h : g_c2;

    extern __shared__ char smraw[];
    __half*        bsm  = (__half*)smraw;          // 3 B tiles
    __half*        asmem = bsm + 3 * BTILE;        // 2 A tiles
    unsigned char* bp   = (unsigned char*)(bsm + 5 * BTILE);  // bitmaps

    const int tid = threadIdx.x, wid = tid >> 5, lane = tid & 31;
    const int wm = wid >> 1, wn = wid & 1;
    const int g = lane >> 2, ti2 = (lane & 3) * 2;
    const int m0 = blockIdx.y * 128, n0 = blockIdx.x * 128;

    float mn, mx;
    if (EPI == 2) { mn = __int_as_float(g_mn2); mx = __int_as_float(g_mx2); }
    else          { mn = __int_as_float(g_mn1); mx = __int_as_float(g_mx1); }
    float qsc = 255.0f / (mx - mn);

    // ---- phase 1: quantize source slab -> bitmaps ----
    constexpr int SEGS = SC / 16;
    #pragma unroll 1
    for (int u = tid; u < 128 * SEGS; u += 256) {
        int r = u / SEGS, seg = u % SEGS;
        const float4* p;
        if (EPI == 0)      p = (const float4*)(node + (m0 + r) * FN + seg * 16);
        else if (EPI == 1) p = (const float4*)(edge + (size_t)(m0 + r) * 64 + seg * 16);
        else               p = (const float4*)(g_h + (size_t)(m0 + r) * H1 + seg * 16);
        unsigned qw[4];
        #pragma unroll
        for (int j = 0; j < 4; j++) {
            float4 v = p[j];
            qw[j] = qz(v.x, mn, qsc) | (qz(v.y, mn, qsc) << 8) |
                    (qz(v.z, mn, qsc) << 16) | (qz(v.w, mn, qsc) << 24);
        }
        unsigned long long x0 = (unsigned long long)qw[0] | ((unsigned long long)qw[1] << 32);
        unsigned long long x1 = (unsigned long long)qw[2] | ((unsigned long long)qw[3] << 32);
        #pragma unroll
        for (int b = 0; b < 8; b++) {
            unsigned short w16 = (unsigned short)(bits8(x0, b) | (bits8(x1, b) << 8));
            *(unsigned short*)(bp + (b * 128 + r) * BPR + seg * 2) = w16;
        }
    }
    __syncthreads();   // bitmaps complete BEFORE any expandA reads them (R11 bug fix)

    // ---- k-loop ----
    float acc[2][8][4];
    #pragma unroll
    for (int a = 0; a < 2; a++)
        #pragma unroll
        for (int b = 0; b < 8; b++)
            #pragma unroll
            for (int c = 0; c < 4; c++) acc[a][b][c] = 0.f;

    auto stagePlane = [&](int s, int& b, int& i0) {
        if (s < KTH) { b = s / SPP; i0 = (s % SPP) * 64; }
        else         { int s2 = s - KTH; b = 4 + s2 / SPP; i0 = (s2 % SPP) * 64; }
    };

    auto loadB = [&](int s) {
        const __half* W; int rs, kofs;
        if (s < KTH) { W = Whi; rs = KHI; kofs = s * 64; }
        else         { W = Wlo; rs = KLO; kofs = (s - KTH) * 64; }
        __half* bs = bsm + (s % 3) * BTILE;
        #pragma unroll
        for (int it2 = 0; it2 < 4; it2++) {
            int cid = tid + it2 * 256;
            int r = cid >> 3, c = (cid & 7) * 8;
            cp_async16(&bs[r * SROW + c], W + (size_t)(n0 + r) * rs + kofs + c);
        }
        asm volatile("cp.async.commit_group;\n");
    };

    // expand stage-s A tile (128x64 binary fp16) from bitmaps into buffer s&1
    const int er = tid >> 1, ehf = tid & 1;
    auto expandA = [&](int s) {
        int b, i0; stagePlane(s, b, i0);
        __half* as2 = asmem + (s & 1) * BTILE;
        unsigned w = *(const unsigned*)(bp + (b * 128 + er) * BPR + (i0 >> 3) + ehf * 4);
        #pragma unroll
        for (int j = 0; j < 4; j++) {
            unsigned bt = w >> (8 * j);
            uint4 v;
            v.x = (bt & 1u)        * 0x3C00u | ((bt >> 1) & 1u) * 0x3C000000u;
            v.y = ((bt >> 2) & 1u) * 0x3C00u | ((bt >> 3) & 1u) * 0x3C000000u;
            v.z = ((bt >> 4) & 1u) * 0x3C00u | ((bt >> 5) & 1u) * 0x3C000000u;
            v.w = ((bt >> 6) & 1u) * 0x3C00u | ((bt >> 7) & 1u) * 0x3C000000u;
            *(uint4*)(as2 + er * SROW + ehf * 32 + j * 8) = v;
        }
    };

    const int lm = lane >> 3, lr = lane & 7;
    const int lmbase = (wn * 64 + (lm >> 1) * 8 + lr) * SROW + (lm & 1) * 8;   // B
    const int albase = ((lm & 1) * 8 + lr) * SROW + (lm >> 1) * 8;             // A

    loadB(0);
    loadB(1);
    expandA(0);
    __syncthreads();   // A(0) visible
    #pragma unroll 1
    for (int s = 0; s < NST; s++) {
        if (s + 1 < NST) asm volatile("cp.async.wait_group 1;\n");
        else             asm volatile("cp.async.wait_group 0;\n");
        __syncthreads();                       // prev-iter reads done; B(s) visible
        if (s + 1 < NST) expandA(s + 1);
        if (s + 2 < NST) loadB(s + 2);

        const __half* as2 = asmem + (s & 1) * BTILE;
        const __half* bs  = bsm + (s % 3) * BTILE;

        #pragma unroll
        for (int kk = 0; kk < 4; kk++) {
            unsigned af[2][4];
            #pragma unroll
            for (int mt = 0; mt < 2; mt++)
                ldmx4(af[mt][0], af[mt][1], af[mt][2], af[mt][3],
                      as2 + albase + (wm * 32 + mt * 16) * SROW + kk * 16);
            unsigned bq[8][2];
            #pragma unroll
            for (int p = 0; p < 4; p++)
                ldmx4(bq[2 * p][0], bq[2 * p][1], bq[2 * p + 1][0], bq[2 * p + 1][1],
                      bs + lmbase + p * (16 * SROW) + kk * 16);
            #pragma unroll
            for (int mt = 0; mt < 2; mt++)
                #pragma unroll
                for (int nt = 0; nt < 8; nt++)
                    asm volatile(
                        "mma.sync.aligned.m16n8k16.row.col.f32.f16.f16.f32 "
                        "{%0,%1,%2,%3},{%4,%5,%6,%7},{%8,%9},{%0,%1,%2,%3};"
                        : "+f"(acc[mt][nt][0]), "+f"(acc[mt][nt][1]),
                          "+f"(acc[mt][nt][2]), "+f"(acc[mt][nt][3])
                        : "r"(af[mt][0]), "r"(af[mt][1]), "r"(af[mt][2]), "r"(af[mt][3]),
                          "r"(bq[nt][0]), "r"(bq[nt][1]));
        }
    }

    // ---- epilogue ----
    if (EPI == 0) {
        #pragma unroll
        for (int mt = 0; mt < 2; mt++)
            #pragma unroll
            for (int nt = 0; nt < 8; nt++)
                #pragma unroll
                for (int c = 0; c < 4; c++) {
                    int row = m0 + wm * 32 + mt * 16 + g + ((c & 2) << 2);
                    int col = n0 + wn * 64 + nt * 8 + ti2 + (c & 1);
                    out[row * H1 + col] = acc[mt][nt][c];
                }
    } else if (EPI == 1) {
        float sc = (mx - mn) * (1.0f / 255.0f);
        float lmn = __int_as_float(0x7f800000), lmx = -lmn;
        #pragma unroll
        for (int mt = 0; mt < 2; mt++)
            #pragma unroll
            for (int nt = 0; nt < 8; nt++)
                #pragma unroll
                for (int c = 0; c < 4; c++) {
                    int row = m0 + wm * 32 + mt * 16 + g + ((c & 2) << 2);
                    int col = n0 + wn * 64 + nt * 8 + ti2 + (c & 1);
                    float z = acc[mt][nt][c] + g_zn[(row / NBRN) * H1 + col];
                    float hv = z * sc + mn * S[col];
                    hv = fmaxf(hv, 0.f);
                    out[(size_t)row * N + col] = hv;
                    lmn = fminf(lmn, hv); lmx = fmaxf(lmx, hv);
                }
        #pragma unroll
        for (int o = 16; o; o >>= 1) {
            lmn = fminf(lmn, __shfl_xor_sync(~0u, lmn, o));
            lmx = fmaxf(lmx, __shfl_xor_sync(~0u, lmx, o));
        }
        if (lane == 0) { atomicMinF(&g_mn2, lmn); atomicMaxF(&g_mx2, lmx); }
    } else {
        float sc = (mx - mn) * (1.0f / 255.0f);
        #pragma unroll
        for (int mt = 0; mt < 2; mt++)
            #pragma unroll
            for (int nt = 0; nt < 8; nt++)
                #pragma unroll
                for (int c = 0; c < 4; c++) {
                    int row = m0 + wm * 32 + mt * 16 + g + ((c & 2) << 2);
                    int col = n0 + wn * 64 + nt * 8 + ti2 + (c & 1);
                    out[(size_t)row * N + col] = acc[mt][nt][c] * sc + mn * S[col];
                }
    }
}

// sigmoid(gate)*tanh(extract)*mask, summed over 12 neighbors
__global__ void k_gate(const float* __restrict__ mask) {
    int idx = blockIdx.x * 256 + threadIdx.x;
    int ba = idx >> 6, j = idx & 63;
    float acc = 0.f;
    #pragma unroll
    for (int nb = 0; nb < NBRN; nb++) {
        int m = ba * NBRN + nb;
        float gv = g_c2[m * H2 + j];
        float ev = g_c2[m * H2 + 64 + j];
        acc += (1.f / (1.f + expf(-gv))) * tanhf(ev) * mask[m];
    }
    g_ns[idx] = acc;
}

// deterministic per-feature BN statistics
__global__ void k_stats() {
    int j = blockIdx.x, t = threadIdx.x;
    __shared__ float red[256];
    __shared__ float mean_s;
    float s = 0.f;
    for (int r = t; r < BA_ROWS; r += 256) s += g_ns[r * FN + j];
    red[t] = s; __syncthreads();
    #pragma unroll
    for (int k = 128; k; k >>= 1) { if (t < k) red[t] += red[t + k]; __syncthreads(); }
    if (t == 0) mean_s = red[0] / (float)BA_ROWS;
    __syncthreads();
    float mean = mean_s, s2 = 0.f;
    for (int r = t; r < BA_ROWS; r += 256) { float d = g_ns[r * FN + j] - mean; s2 += d * d; }
    red[t] = s2; __syncthreads();
    #pragma unroll
    for (int k = 128; k; k >>= 1) { if (t < k) red[t] += red[t + k]; __syncthreads(); }
    if (t == 0) { g_mean[j] = mean; g_var[j] = red[0] / (float)BA_ROWS; }
}

__global__ void k_final(const float* __restrict__ node, const float* __restrict__ gamma,
                        const float* __restrict__ beta, float* __restrict__ out) {
    int idx = blockIdx.x * 256 + threadIdx.x;
    int j = idx & 63;
    float bn = (g_ns[idx] - g_mean[j]) / sqrtf(g_var[j] + 1e-5f) * gamma[j] + beta[j];
    out[idx] = fmaxf(node[idx] + bn, 0.f);
}

// ---------------- launcher ----------------
extern "C" void kernel_launch(void* const* d_in, const int* in_sizes, int n_in,
                              void* d_out, int out_size) {
    const float* node  = (const float*)d_in[0];
    const float* edge  = (const float*)d_in[1];
    const float* maskp = (const float*)d_in[2];
    const float* cond1 = (const float*)d_in[3];
    const float* cond2 = (const float*)d_in[4];
    const float* eps1  = (const float*)d_in[5];
    const float* eps2  = (const float*)d_in[6];
    const float* gamma = (const float*)d_in[7];
    const float* beta  = (const float*)d_in[8];
    float* out = (float*)d_out;

    // smem: 3 B tiles + 2 A tiles (5 x 128x72 fp16) + bitmaps
    const int SMEM01 = 5 * 128 * 72 * 2 + 8 * 128 * (64 / 8 + 8);    // 108544
    const int SMEM2  = 5 * 128 * 72 * 2 + 8 * 128 * (512 / 8 + 8);   // 165888
    cudaFuncSetAttribute(k_tc<0>, cudaFuncAttributeMaxDynamicSharedMemorySize, SMEM01);
    cudaFuncSetAttribute(k_tc<1>, cudaFuncAttributeMaxDynamicSharedMemorySize, SMEM01);
    cudaFuncSetAttribute(k_tc<2>, cudaFuncAttributeMaxDynamicSharedMemorySize, SMEM2);

    k_init<<<1, 1>>>();
    k_minmax<<<(NODE_N + EDGE_N) / 256, 256>>>(node, edge);
    k_prep1<<<H1, 128>>>(cond1, eps1);
    k_prep2<<<H2, 256>>>(cond2, eps2);
    k_tc<0><<<dim3(H1 / 128, BA_ROWS / 128), 256, SMEM01>>>(node, edge);
    k_tc<1><<<dim3(H1 / 128, M_ROWS / 128), 256, SMEM01>>>(node, edge);
    k_tc<2><<<dim3(1, M_ROWS / 128), 256, SMEM2>>>(nullptr, nullptr);
    k_gate<<<(BA_ROWS * FN) / 256, 256>>>(maskp);
    k_stats<<<FN, 256>>>();
    k_final<<<(BA_ROWS * FN) / 256, 256>>>(node, gamma, beta, out);
}